// round 14
// baseline (speedup 1.0000x reference)
#include <cuda_runtime.h>
#include <cuda_bf16.h>
#include <mma.h>
#include <cstdint>

using namespace nvcuda;

#define Bb 16
#define Nn 4096
#define Dd 64

// Scratch (device globals; allocation in kernel_launch is forbidden)
__device__ __align__(16) __nv_bfloat16 g_Wb[(size_t)Nn * Nn];      // W bf16, diag=0
__device__ __align__(16) __nv_bfloat16 g_Xb[(size_t)Bb * Dd * Nn]; // X^T: [b*64+d][j]
__device__ __align__(16) float         g_P [(size_t)Bb * Nn * Dd]; // X @ r_proj
__device__ float g_l1[Nn];
__device__ float g_l2[Nn];

// ---------------------------------------------------------------------------
// Kernel A: threshold + diagonal-skip scatter via smem staging; vectorized
// global stores; per-row l1/l2.
// ---------------------------------------------------------------------------
__global__ __launch_bounds__(256)
void prep_kernel(const float* __restrict__ inc, float* __restrict__ inc_all) {
    __shared__ float srow[Nn];
    __shared__ float smx[256], sss[256];
    int i   = blockIdx.x;
    int tid = threadIdx.x;
    const float* row = inc + (size_t)i * (Nn - 1);

    if (tid == 0) srow[i] = 0.f;
    float mx = 0.f, ss = 0.f;
    #pragma unroll 4
    for (int j = tid; j < Nn - 1; j += 256) {
        float x = __ldg(row + j);
        float v = (x > 0.01f) ? x : 0.f;
        srow[j + (j >= i ? 1 : 0)] = v;
        mx = fmaxf(mx, v);
        ss += v * v;
    }
    smx[tid] = mx; sss[tid] = ss;
    __syncthreads();

    float* orow = inc_all + (size_t)i * Nn;
    int iv = i >> 2;
    #pragma unroll
    for (int t = 0; t < 4; t++) {
        int c4 = tid + t * 256;
        float4 v = reinterpret_cast<const float4*>(srow)[c4];
        if (c4 == iv) reinterpret_cast<float*>(&v)[i & 3] = 1.f;
        reinterpret_cast<float4*>(orow)[c4] = v;
    }

    __nv_bfloat16* wrow = g_Wb + (size_t)i * Nn;
    #pragma unroll
    for (int t = 0; t < 2; t++) {
        int c8 = tid + t * 256;
        const float* s8 = srow + c8 * 8;
        __nv_bfloat162 h0 = __floats2bfloat162_rn(s8[0], s8[1]);
        __nv_bfloat162 h1 = __floats2bfloat162_rn(s8[2], s8[3]);
        __nv_bfloat162 h2 = __floats2bfloat162_rn(s8[4], s8[5]);
        __nv_bfloat162 h3 = __floats2bfloat162_rn(s8[6], s8[7]);
        uint4 u;
        u.x = *reinterpret_cast<unsigned*>(&h0);
        u.y = *reinterpret_cast<unsigned*>(&h1);
        u.z = *reinterpret_cast<unsigned*>(&h2);
        u.w = *reinterpret_cast<unsigned*>(&h3);
        reinterpret_cast<uint4*>(wrow)[c8] = u;
    }

    for (int s = 128; s > 0; s >>= 1) {
        if (tid < s) {
            smx[tid] = fmaxf(smx[tid], smx[tid + s]);
            sss[tid] += sss[tid + s];
        }
        __syncthreads();
    }
    if (tid == 0) {
        g_l1[i] = smx[0];
        g_l2[i] = sqrtf(sss[0]);
    }
}

// ---------------------------------------------------------------------------
// Kernel B: X_proj = X @ r_proj (fp32) and bf16 transpose of X into g_Xb.
// ---------------------------------------------------------------------------
__global__ __launch_bounds__(256)
void proj_kernel(const float* __restrict__ X, const float* __restrict__ rp) {
    __shared__ float Rs[64 * 64];
    __shared__ float Xs[32][65];
    int tid = threadIdx.x;
    int r0  = blockIdx.x * 32;

    for (int t = tid; t < 4096; t += 256) Rs[t] = rp[t];
    #pragma unroll
    for (int t = 0; t < 8; t++) {
        int e = tid + t * 256;
        Xs[e >> 6][e & 63] = X[(size_t)(r0 + (e >> 6)) * 64 + (e & 63)];
    }
    __syncthreads();

    #pragma unroll
    for (int t = 0; t < 8; t++) {
        int e = tid + t * 256;
        int row = e >> 6, d = e & 63;
        float acc = 0.f;
        #pragma unroll
        for (int k = 0; k < 64; k++) acc += Xs[row][k] * Rs[k * 64 + d];
        g_P[(size_t)(r0 + row) * 64 + d] = acc;
    }

    int b  = r0 >> 12;
    int ib = r0 & (Nn - 1);
    #pragma unroll
    for (int t = 0; t < 8; t++) {
        int e  = tid + t * 256;
        int il = e & 31, d = e >> 5;
        g_Xb[(size_t)(b * 64 + d) * Nn + ib + il] = __float2bfloat16(Xs[il][d]);
    }
}

// ---------------------------------------------------------------------------
// Kernel C: recon = W @ X (bf16 WMMA / HMMA). Block 128x256xK, 8 warps with
// 64x64 warp tiles, KC=64 stages, 3-deep cp.async ring, ONE sync per stage,
// fused loss epilogue (warp column range == one batch's D-slice).
// ---------------------------------------------------------------------------
#define MT 128
#define NT 256
#define KC 64
#define STAGES (Nn / KC)                 // 64
#define LDA 72                           // bf16 smem stride (144B, 16B-aligned)
#define AELE (MT * LDA)                  // 9216 bf16
#define BELE (NT * LDA)                  // 18432 bf16
#define BUFELE (AELE + BELE)             // 27648 bf16 = 55296 B / stage
#define NBUF 3
#define LDP 260   // fp32 epilogue stride: 1040B = 65x16B (store_matrix_sync
                  // needs 16B-multiple ldm; 257 was the round-8..11 bug) and
                  // phase-of-8 float4 reads hit banks 4t..4t+3 (conflict-free)

__device__ __forceinline__ void cp16(void* s, const void* g) {
    unsigned sa = (unsigned)__cvta_generic_to_shared(s);
    asm volatile("cp.async.cg.shared.global [%0], [%1], 16;" :: "r"(sa), "l"(g));
}

extern __shared__ unsigned char dynsmem[];

__global__ __launch_bounds__(256, 1)
void gemm_loss_kernel(float* __restrict__ out) {
    __nv_bfloat16* sm = reinterpret_cast<__nv_bfloat16*>(dynsmem);

    int tid  = threadIdx.x;
    int warp = tid >> 5;
    int wm   = warp & 1;                 // 2 warps along M (64 rows each)
    int wn   = warp >> 1;                // 4 warps along N (64 cols = 1 batch)
    int i0   = blockIdx.x * MT;
    int c0   = blockIdx.y * NT;

    const __nv_bfloat16* Ag = g_Wb + (size_t)i0 * Nn;
    const __nv_bfloat16* Bg = g_Xb + (size_t)c0 * Nn;

    wmma::fragment<wmma::accumulator, 16, 16, 16, float> acc[4][4];
    #pragma unroll
    for (int mi = 0; mi < 4; mi++)
        #pragma unroll
        for (int ni = 0; ni < 4; ni++) wmma::fill_fragment(acc[mi][ni], 0.f);

    auto load_stage = [&](int s, int buf) {
        __nv_bfloat16* As = sm + buf * BUFELE;
        __nv_bfloat16* Bs = As + AELE;
        int kt = s * KC;
        #pragma unroll
        for (int t = 0; t < 4; t++) {            // A: 1024 x 16B chunks
            int idx = tid + t * 256;
            int r = idx >> 3, c = (idx & 7) * 8;
            cp16(As + r * LDA + c, Ag + (size_t)r * Nn + kt + c);
        }
        #pragma unroll
        for (int t = 0; t < 8; t++) {            // B: 2048 x 16B chunks
            int idx = tid + t * 256;
            int r = idx >> 3, c = (idx & 7) * 8;
            cp16(Bs + r * LDA + c, Bg + (size_t)r * Nn + kt + c);
        }
    };

    load_stage(0, 0); asm volatile("cp.async.commit_group;");
    load_stage(1, 1); asm volatile("cp.async.commit_group;");

    #pragma unroll 1
    for (int s = 0; s < STAGES; s++) {
        if (s + 2 < STAGES) {
            asm volatile("cp.async.wait_group 1;");
        } else {
            asm volatile("cp.async.wait_group 0;");
        }
        __syncthreads();                          // stage s visible; s-1 compute done

        if (s + 2 < STAGES) {                     // overwrite buf (s-1)%NBUF: safe
            load_stage(s + 2, (s + 2) % NBUF);
            asm volatile("cp.async.commit_group;");
        }

        const __nv_bfloat16* As = sm + (s % NBUF) * BUFELE;
        const __nv_bfloat16* Bs = As + AELE;
        #pragma unroll
        for (int kk = 0; kk < KC; kk += 16) {
            wmma::fragment<wmma::matrix_a, 16, 16, 16, __nv_bfloat16, wmma::row_major> a[4];
            wmma::fragment<wmma::matrix_b, 16, 16, 16, __nv_bfloat16, wmma::col_major> b[4];
            #pragma unroll
            for (int mi = 0; mi < 4; mi++)
                wmma::load_matrix_sync(a[mi], As + (wm * 64 + mi * 16) * LDA + kk, LDA);
            #pragma unroll
            for (int ni = 0; ni < 4; ni++)
                wmma::load_matrix_sync(b[ni], Bs + (wn * 64 + ni * 16) * LDA + kk, LDA);
            #pragma unroll
            for (int mi = 0; mi < 4; mi++)
                #pragma unroll
                for (int ni = 0; ni < 4; ni++)
                    wmma::mma_sync(acc[mi][ni], a[mi], b[ni], acc[mi][ni]);
        }
    }
    __syncthreads();                              // all compute done before smem reuse

    // ---- Epilogue: acc -> smem [128][LDP] (cols = 4 batches x 64), reduce.
    float* Rs = reinterpret_cast<float*>(dynsmem);
    #pragma unroll
    for (int mi = 0; mi < 4; mi++)
        #pragma unroll
        for (int ni = 0; ni < 4; ni++)
            wmma::store_matrix_sync(Rs + (wm * 64 + mi * 16) * LDP + wn * 64 + ni * 16,
                                    acc[mi][ni], LDP, wmma::mem_row_major);
    __syncthreads();

    #pragma unroll
    for (int p = 0; p < 2; p++) {
        int id  = tid + p * 256;                  // 0..511
        int row = id & 127;
        int bl  = id >> 7;                        // 0..3
        int ct  = blockIdx.y * 4 + bl;
        int i   = i0 + row;
        const float4* P = reinterpret_cast<const float4*>(
            g_P + ((size_t)ct * Nn + i) * 64);
        const float* Rrow = Rs + row * LDP + bl * 64;
        float sum = 0.f;
        #pragma unroll
        for (int k = 0; k < 16; k++) {
            float4 pv = __ldg(P + k);
            float d0 = pv.x - Rrow[k * 4 + 0];
            float d1 = pv.y - Rrow[k * 4 + 1];
            float d2 = pv.z - Rrow[k * 4 + 2];
            float d3 = pv.w - Rrow[k * 4 + 3];
            sum += d0 * d0 + d1 * d1 + d2 * d2 + d3 * d3;
        }
        out[ct * Nn + i] = 0.2f * sqrtf(sum) + g_l1[i] + 0.001f * g_l2[i];
    }
}

// ---------------------------------------------------------------------------
extern "C" void kernel_launch(void* const* d_in, const int* in_sizes, int n_in,
                              void* d_out, int out_size) {
    const float* X   = (const float*)d_in[0];   // [16,4096,64]
    const float* rp  = (const float*)d_in[1];   // [64,64]
    const float* inc = (const float*)d_in[2];   // [4096,4095]
    float* out     = (float*)d_out;             // loss [16,4096]
    float* inc_all = out + (size_t)Bb * Nn;     // incidence_all [4096,4096]

    const int pipe_bytes = NBUF * BUFELE * 2;               // 165888
    const int epi_bytes  = MT * LDP * 4;                    // 133120
    const int smem_bytes = pipe_bytes > epi_bytes ? pipe_bytes : epi_bytes;
    cudaFuncSetAttribute(gemm_loss_kernel,
                         cudaFuncAttributeMaxDynamicSharedMemorySize, smem_bytes);

    prep_kernel<<<Nn, 256>>>(inc, inc_all);
    proj_kernel<<<(Bb * Nn) / 32, 256>>>(X, rp);
    dim3 g(Nn / MT, (Bb * Dd) / NT);            // (32, 4)
    gemm_loss_kernel<<<g, 256, smem_bytes>>>(out);
}

// round 15
// speedup vs baseline: 1.4815x; 1.4815x over previous
#include <cuda_runtime.h>
#include <cuda_bf16.h>
#include <mma.h>
#include <cstdint>

using namespace nvcuda;

#define Bb 16
#define Nn 4096
#define Dd 64

// Scratch (device globals; allocation in kernel_launch is forbidden)
__device__ __align__(16) __nv_bfloat16 g_Wb[(size_t)Nn * Nn];      // W bf16, diag=0
__device__ __align__(16) __nv_bfloat16 g_Xb[(size_t)Bb * Dd * Nn]; // X^T: [b*64+d][j]
__device__ __align__(16) float         g_P [(size_t)Bb * Nn * Dd]; // X @ r_proj
__device__ float g_l1[Nn];
__device__ float g_l2[Nn];

// ---------------------------------------------------------------------------
// Kernel A: threshold + diagonal-skip scatter via smem staging; vectorized
// global stores; per-row l1/l2.
// ---------------------------------------------------------------------------
__global__ __launch_bounds__(256)
void prep_kernel(const float* __restrict__ inc, float* __restrict__ inc_all) {
    __shared__ float srow[Nn];
    __shared__ float smx[256], sss[256];
    int i   = blockIdx.x;
    int tid = threadIdx.x;
    const float* row = inc + (size_t)i * (Nn - 1);

    if (tid == 0) srow[i] = 0.f;
    float mx = 0.f, ss = 0.f;
    #pragma unroll 4
    for (int j = tid; j < Nn - 1; j += 256) {
        float x = __ldg(row + j);
        float v = (x > 0.01f) ? x : 0.f;
        srow[j + (j >= i ? 1 : 0)] = v;
        mx = fmaxf(mx, v);
        ss += v * v;
    }
    smx[tid] = mx; sss[tid] = ss;
    __syncthreads();

    float* orow = inc_all + (size_t)i * Nn;
    int iv = i >> 2;
    #pragma unroll
    for (int t = 0; t < 4; t++) {
        int c4 = tid + t * 256;
        float4 v = reinterpret_cast<const float4*>(srow)[c4];
        if (c4 == iv) reinterpret_cast<float*>(&v)[i & 3] = 1.f;
        reinterpret_cast<float4*>(orow)[c4] = v;
    }

    __nv_bfloat16* wrow = g_Wb + (size_t)i * Nn;
    #pragma unroll
    for (int t = 0; t < 2; t++) {
        int c8 = tid + t * 256;
        const float* s8 = srow + c8 * 8;
        __nv_bfloat162 h0 = __floats2bfloat162_rn(s8[0], s8[1]);
        __nv_bfloat162 h1 = __floats2bfloat162_rn(s8[2], s8[3]);
        __nv_bfloat162 h2 = __floats2bfloat162_rn(s8[4], s8[5]);
        __nv_bfloat162 h3 = __floats2bfloat162_rn(s8[6], s8[7]);
        uint4 u;
        u.x = *reinterpret_cast<unsigned*>(&h0);
        u.y = *reinterpret_cast<unsigned*>(&h1);
        u.z = *reinterpret_cast<unsigned*>(&h2);
        u.w = *reinterpret_cast<unsigned*>(&h3);
        reinterpret_cast<uint4*>(wrow)[c8] = u;
    }

    for (int s = 128; s > 0; s >>= 1) {
        if (tid < s) {
            smx[tid] = fmaxf(smx[tid], smx[tid + s]);
            sss[tid] += sss[tid + s];
        }
        __syncthreads();
    }
    if (tid == 0) {
        g_l1[i] = smx[0];
        g_l2[i] = sqrtf(sss[0]);
    }
}

// ---------------------------------------------------------------------------
// Kernel B: X_proj = X @ r_proj (fp32) and bf16 transpose of X into g_Xb.
// ---------------------------------------------------------------------------
__global__ __launch_bounds__(256)
void proj_kernel(const float* __restrict__ X, const float* __restrict__ rp) {
    __shared__ float Rs[64 * 64];
    __shared__ float Xs[32][65];
    int tid = threadIdx.x;
    int r0  = blockIdx.x * 32;

    for (int t = tid; t < 4096; t += 256) Rs[t] = rp[t];
    #pragma unroll
    for (int t = 0; t < 8; t++) {
        int e = tid + t * 256;
        Xs[e >> 6][e & 63] = X[(size_t)(r0 + (e >> 6)) * 64 + (e & 63)];
    }
    __syncthreads();

    #pragma unroll
    for (int t = 0; t < 8; t++) {
        int e = tid + t * 256;
        int row = e >> 6, d = e & 63;
        float acc = 0.f;
        #pragma unroll
        for (int k = 0; k < 64; k++) acc += Xs[row][k] * Rs[k * 64 + d];
        g_P[(size_t)(r0 + row) * 64 + d] = acc;
    }

    int b  = r0 >> 12;
    int ib = r0 & (Nn - 1);
    #pragma unroll
    for (int t = 0; t < 8; t++) {
        int e  = tid + t * 256;
        int il = e & 31, d = e >> 5;
        g_Xb[(size_t)(b * 64 + d) * Nn + ib + il] = __float2bfloat16(Xs[il][d]);
    }
}

// ---------------------------------------------------------------------------
// Kernel C: recon = W @ X (bf16 WMMA / HMMA). Block 128x256xK. 16 warps
// (512 thr, 4/SMSP for latency hiding), 32x64 warp tiles (acc 2x4).
// 3-deep cp.async ring, ONE __syncthreads per stage, fused loss epilogue.
// ---------------------------------------------------------------------------
#define MT 128
#define NT 256
#define KC 64
#define STAGES (Nn / KC)                 // 64
#define LDA 72                           // bf16 smem stride (144B, 16B-aligned)
#define AELE (MT * LDA)                  // 9216 bf16
#define BELE (NT * LDA)                  // 18432 bf16
#define BUFELE (AELE + BELE)             // 27648 bf16 = 55296 B / stage
#define NBUF 3
#define LDP 260   // fp32 epilogue stride: 1040B = 65x16B (16B-multiple ldm
                  // required by store_matrix_sync) and conflict-free float4 rows

__device__ __forceinline__ void cp16(void* s, const void* g) {
    unsigned sa = (unsigned)__cvta_generic_to_shared(s);
    asm volatile("cp.async.cg.shared.global [%0], [%1], 16;" :: "r"(sa), "l"(g));
}

extern __shared__ unsigned char dynsmem[];

__global__ __launch_bounds__(512, 1)
void gemm_loss_kernel(float* __restrict__ out) {
    __nv_bfloat16* sm = reinterpret_cast<__nv_bfloat16*>(dynsmem);

    int tid  = threadIdx.x;
    int warp = tid >> 5;
    int wm   = warp & 3;                 // 4 warps along M (32 rows each)
    int wn   = warp >> 2;                // 4 warps along N (64 cols = 1 batch)
    int i0   = blockIdx.x * MT;
    int c0   = blockIdx.y * NT;

    const __nv_bfloat16* Ag = g_Wb + (size_t)i0 * Nn;
    const __nv_bfloat16* Bg = g_Xb + (size_t)c0 * Nn;

    wmma::fragment<wmma::accumulator, 16, 16, 16, float> acc[2][4];
    #pragma unroll
    for (int mi = 0; mi < 2; mi++)
        #pragma unroll
        for (int ni = 0; ni < 4; ni++) wmma::fill_fragment(acc[mi][ni], 0.f);

    auto load_stage = [&](int s, int buf) {
        __nv_bfloat16* As = sm + buf * BUFELE;
        __nv_bfloat16* Bs = As + AELE;
        int kt = s * KC;
        #pragma unroll
        for (int t = 0; t < 2; t++) {            // A: 1024 x 16B chunks
            int idx = tid + t * 512;
            int r = idx >> 3, c = (idx & 7) * 8;
            cp16(As + r * LDA + c, Ag + (size_t)r * Nn + kt + c);
        }
        #pragma unroll
        for (int t = 0; t < 4; t++) {            // B: 2048 x 16B chunks
            int idx = tid + t * 512;
            int r = idx >> 3, c = (idx & 7) * 8;
            cp16(Bs + r * LDA + c, Bg + (size_t)r * Nn + kt + c);
        }
    };

    load_stage(0, 0); asm volatile("cp.async.commit_group;");
    load_stage(1, 1); asm volatile("cp.async.commit_group;");

    #pragma unroll 1
    for (int s = 0; s < STAGES; s++) {
        if (s + 2 < STAGES) {
            asm volatile("cp.async.wait_group 1;");
        } else {
            asm volatile("cp.async.wait_group 0;");
        }
        __syncthreads();                          // stage s visible; s-1 compute done

        if (s + 2 < STAGES) {                     // overwrites buf (s-1)%NBUF: WAR-safe
            load_stage(s + 2, (s + 2) % NBUF);
            asm volatile("cp.async.commit_group;");
        }

        const __nv_bfloat16* As = sm + (s % NBUF) * BUFELE;
        const __nv_bfloat16* Bs = As + AELE;
        #pragma unroll
        for (int kk = 0; kk < KC; kk += 16) {
            wmma::fragment<wmma::matrix_a, 16, 16, 16, __nv_bfloat16, wmma::row_major> a[2];
            wmma::fragment<wmma::matrix_b, 16, 16, 16, __nv_bfloat16, wmma::col_major> b[4];
            #pragma unroll
            for (int mi = 0; mi < 2; mi++)
                wmma::load_matrix_sync(a[mi], As + (wm * 32 + mi * 16) * LDA + kk, LDA);
            #pragma unroll
            for (int ni = 0; ni < 4; ni++)
                wmma::load_matrix_sync(b[ni], Bs + (wn * 64 + ni * 16) * LDA + kk, LDA);
            #pragma unroll
            for (int mi = 0; mi < 2; mi++)
                #pragma unroll
                for (int ni = 0; ni < 4; ni++)
                    wmma::mma_sync(acc[mi][ni], a[mi], b[ni], acc[mi][ni]);
        }
    }
    __syncthreads();                              // all compute done before smem reuse

    // ---- Epilogue: acc -> smem [128][LDP] (cols = 4 batches x 64), reduce.
    float* Rs = reinterpret_cast<float*>(dynsmem);
    #pragma unroll
    for (int mi = 0; mi < 2; mi++)
        #pragma unroll
        for (int ni = 0; ni < 4; ni++)
            wmma::store_matrix_sync(Rs + (wm * 32 + mi * 16) * LDP + wn * 64 + ni * 16,
                                    acc[mi][ni], LDP, wmma::mem_row_major);
    __syncthreads();

    {
        int row = tid & 127;
        int bl  = tid >> 7;                       // 0..3
        int ct  = blockIdx.y * 4 + bl;
        int i   = i0 + row;
        const float4* P = reinterpret_cast<const float4*>(
            g_P + ((size_t)ct * Nn + i) * 64);
        const float* Rrow = Rs + row * LDP + bl * 64;
        float sum = 0.f;
        #pragma unroll
        for (int k = 0; k < 16; k++) {
            float4 pv = __ldg(P + k);
            float d0 = pv.x - Rrow[k * 4 + 0];
            float d1 = pv.y - Rrow[k * 4 + 1];
            float d2 = pv.z - Rrow[k * 4 + 2];
            float d3 = pv.w - Rrow[k * 4 + 3];
            sum += d0 * d0 + d1 * d1 + d2 * d2 + d3 * d3;
        }
        out[ct * Nn + i] = 0.2f * sqrtf(sum) + g_l1[i] + 0.001f * g_l2[i];
    }
}

// ---------------------------------------------------------------------------
extern "C" void kernel_launch(void* const* d_in, const int* in_sizes, int n_in,
                              void* d_out, int out_size) {
    const float* X   = (const float*)d_in[0];   // [16,4096,64]
    const float* rp  = (const float*)d_in[1];   // [64,64]
    const float* inc = (const float*)d_in[2];   // [4096,4095]
    float* out     = (float*)d_out;             // loss [16,4096]
    float* inc_all = out + (size_t)Bb * Nn;     // incidence_all [4096,4096]

    const int pipe_bytes = NBUF * BUFELE * 2;               // 165888
    const int epi_bytes  = MT * LDP * 4;                    // 133120
    const int smem_bytes = pipe_bytes > epi_bytes ? pipe_bytes : epi_bytes;
    cudaFuncSetAttribute(gemm_loss_kernel,
                         cudaFuncAttributeMaxDynamicSharedMemorySize, smem_bytes);

    prep_kernel<<<Nn, 256>>>(inc, inc_all);
    proj_kernel<<<(Bb * Nn) / 32, 256>>>(X, rp);
    dim3 g(Nn / MT, (Bb * Dd) / NT);            // (32, 4)
    gemm_loss_kernel<<<g, 512, smem_bytes>>>(out);
}